// round 16
// baseline (speedup 1.0000x reference)
#include <cuda_runtime.h>

// Problem constants
#define BSZ 2
#define NTOK 2048
#define EDIM 1024
#define NHEAD 16
#define HDIM 64
#define FDIM 192   // 3 * HDIM, order: k | q | v

// Scratch (static device memory — no allocation)
__device__ float g_proj[(size_t)BSZ * NHEAD * NTOK * FDIM]; // [z][n][f], z = b*H+h
__device__ float g_sa[(size_t)BSZ * NTOK * EDIM];           // [b][n][e]

// ---------------------------------------------------------------------------
// tf32 helpers
// ---------------------------------------------------------------------------
__device__ __forceinline__ unsigned f2tf(float x) {
    unsigned u;
    asm("cvt.rna.tf32.f32 %0, %1;" : "=r"(u) : "f"(x));
    return u;
}

__device__ __forceinline__ void mma_tf32(float c[4], const unsigned a[4], const unsigned b[2]) {
    asm volatile(
        "mma.sync.aligned.m16n8k8.row.col.f32.tf32.tf32.f32 "
        "{%0,%1,%2,%3},{%4,%5,%6,%7},{%8,%9},{%0,%1,%2,%3};"
        : "+f"(c[0]), "+f"(c[1]), "+f"(c[2]), "+f"(c[3])
        : "r"(a[0]), "r"(a[1]), "r"(a[2]), "r"(a[3]), "r"(b[0]), "r"(b[1]));
}

// ---------------------------------------------------------------------------
// tf32 GEMM: C[128 x 64] tile = A(MxK) @ B(KxN) + bias. 256 threads, 8 warps.
// Round-4 math/indexing, now DOUBLE-BUFFERED smem: one __syncthreads per
// 32-wide K-tile. Stage layout: As[128][36] then Bs[32][68] (6784 u32/stage).
// ---------------------------------------------------------------------------
#define STAGE_U32 (128 * 36 + 32 * 68)
#define GEMM_SMEM_BYTES (2 * STAGE_U32 * 4)

__device__ __forceinline__ void gemm_tf32_tile(
    const float* __restrict__ A, int lda,
    const float* __restrict__ B, int ldb,
    const float* __restrict__ bias,
    float* __restrict__ C, int ldc,
    int K, int bm, int bn, unsigned* smem)
{
    const int t = threadIdx.x;
    const int w = t >> 5, lane = t & 31;
    const int g = lane >> 2, tc = lane & 3;
    const int wm = w >> 1, wn = w & 1;

    const int ar = t >> 3;          // 0..31
    const int ac = (t & 7) << 2;    // 0,4..28
    const int br = t >> 3;          // 0..31
    const int bc = (t & 7) << 3;    // 0,8..56

    float4 aReg[4], bReg[2];

    auto loadG = [&](int k0) {
#pragma unroll
        for (int i = 0; i < 4; i++)
            aReg[i] = *(const float4*)(A + (size_t)(bm + ar + 32 * i) * lda + k0 + ac);
        bReg[0] = *(const float4*)(B + (size_t)(k0 + br) * ldb + bn + bc);
        bReg[1] = *(const float4*)(B + (size_t)(k0 + br) * ldb + bn + bc + 4);
    };

    auto cvtStore = [&](unsigned* S) {
        unsigned* As_ = S;
        unsigned* Bs_ = S + 128 * 36;
#pragma unroll
        for (int i = 0; i < 4; i++) {
            const int r = ar + 32 * i;
            As_[(ac + 0) + r * 36] = 0;  // placeholder overwritten below (keeps symmetry)
            uint4 u;
            u.x = f2tf(aReg[i].x); u.y = f2tf(aReg[i].y);
            u.z = f2tf(aReg[i].z); u.w = f2tf(aReg[i].w);
            *(uint4*)&As_[r * 36 + ac] = u;
        }
        uint4 u0, u1;
        u0.x = f2tf(bReg[0].x); u0.y = f2tf(bReg[0].y);
        u0.z = f2tf(bReg[0].z); u0.w = f2tf(bReg[0].w);
        u1.x = f2tf(bReg[1].x); u1.y = f2tf(bReg[1].y);
        u1.z = f2tf(bReg[1].z); u1.w = f2tf(bReg[1].w);
        *(uint4*)&Bs_[br * 68 + bc] = u0;
        *(uint4*)&Bs_[br * 68 + bc + 4] = u1;
    };

    float acc[2][4][4] = {};

    loadG(0);
    cvtStore(smem);              // fill stage 0
    __syncthreads();

    const int NT = K / 32;
    int s = 0;
#pragma unroll 1
    for (int kt = 0; kt < NT; kt++) {
        if (kt + 1 < NT) loadG((kt + 1) * 32);

        const unsigned* As_ = smem + s * STAGE_U32;
        const unsigned* Bs_ = As_ + 128 * 36;
#pragma unroll
        for (int ks = 0; ks < 4; ks++) {
            const int k8 = ks << 3;
            unsigned af[2][4];
#pragma unroll
            for (int mt = 0; mt < 2; mt++) {
                const int m = wm * 32 + mt * 16 + g;
                af[mt][0] = As_[m * 36 + k8 + tc];
                af[mt][1] = As_[(m + 8) * 36 + k8 + tc];
                af[mt][2] = As_[m * 36 + k8 + tc + 4];
                af[mt][3] = As_[(m + 8) * 36 + k8 + tc + 4];
            }
#pragma unroll
            for (int j = 0; j < 4; j++) {
                const int n = wn * 32 + j * 8 + g;
                unsigned bf[2];
                bf[0] = Bs_[(k8 + tc) * 68 + n];
                bf[1] = Bs_[(k8 + tc + 4) * 68 + n];
#pragma unroll
                for (int mt = 0; mt < 2; mt++)
                    mma_tf32(acc[mt][j], af[mt], bf);
            }
        }

        if (kt + 1 < NT) cvtStore(smem + (s ^ 1) * STAGE_U32);
        __syncthreads();
        s ^= 1;
    }

    // Epilogue (verbatim round 4)
#pragma unroll
    for (int mt = 0; mt < 2; mt++) {
        const int row0 = bm + wm * 32 + mt * 16 + g;
#pragma unroll
        for (int j = 0; j < 4; j++) {
            const int col = bn + wn * 32 + j * 8 + 2 * tc;
            const float2 bv = *(const float2*)(bias + col);
            float2 o0, o1;
            o0.x = acc[mt][j][0] + bv.x; o0.y = acc[mt][j][1] + bv.y;
            o1.x = acc[mt][j][2] + bv.x; o1.y = acc[mt][j][3] + bv.y;
            *(float2*)(C + (size_t)row0 * ldc + col) = o0;
            *(float2*)(C + (size_t)(row0 + 8) * ldc + col) = o1;
        }
    }
}

// QKV projection: per (b,h): proj[z] = x[b] (N x E) @ Wqkv[h] (E x 192) + bqkv[h]
__global__ void qkv_gemm_kernel(const float* __restrict__ x,
                                const float* __restrict__ Wqkv,
                                const float* __restrict__ bqkv)
{
    extern __shared__ unsigned smg[];
    const int z = blockIdx.z;
    const int b = z >> 4, h = z & 15;
    gemm_tf32_tile(x + (size_t)b * NTOK * EDIM, EDIM,
                   Wqkv + (size_t)h * EDIM * FDIM, FDIM,
                   bqkv + h * FDIM,
                   g_proj + (size_t)z * NTOK * FDIM, FDIM,
                   EDIM, blockIdx.y * 128, blockIdx.x * 64, smg);
}

// Output projection: out = g_sa (B*N x E) @ Wout (E x E) + bout
__global__ void out_gemm_kernel(const float* __restrict__ Wout,
                                const float* __restrict__ bout,
                                float* __restrict__ out)
{
    extern __shared__ unsigned smg[];
    gemm_tf32_tile(g_sa, EDIM, Wout, EDIM, bout, out, EDIM,
                   EDIM, blockIdx.y * 128, blockIdx.x * 64, smg);
}

// ---------------------------------------------------------------------------
// Flash attention with tf32 mma — VERBATIM round 4 (proven, 636.5us run).
// ---------------------------------------------------------------------------
#define ATT_SMEM_WORDS (128 * 68 + 64 * 68 + 64 * 68 + 128 * 68)

__global__ void attn_kernel()
{
    extern __shared__ unsigned sm[];
    unsigned* Qs = sm;                  // [128][68]
    unsigned* Ks = Qs + 128 * 68;       // [64][68]
    unsigned* Vs = Ks + 64 * 68;        // [64][68]
    unsigned* Ps = Vs + 64 * 68;        // [128][68]

    const int z = blockIdx.y;
    const int b = z >> 4, h = z & 15;
    const int qb = blockIdx.x;          // 128-row Q block
    const float* base = g_proj + (size_t)z * NTOK * FDIM;

    const int t = threadIdx.x;
    const int w = t >> 5, lane = t & 31;
    const int g = lane >> 2, tc = lane & 3;

    // Load Q (f in [64,128)), scale by 1/8, round to tf32
#pragma unroll
    for (int i = 0; i < 8; i++) {
        int u = t + 256 * i;
        int r = u >> 4, c4 = (u & 15) << 2;
        float4 v = *(const float4*)(base + (size_t)(qb * 128 + r) * FDIM + 64 + c4);
        uint4 q;
        q.x = f2tf(v.x * 0.125f); q.y = f2tf(v.y * 0.125f);
        q.z = f2tf(v.z * 0.125f); q.w = f2tf(v.w * 0.125f);
        *(uint4*)&Qs[r * 68 + c4] = q;
    }

    float m_[2] = { -1e30f, -1e30f };
    float l_[2] = { 0.f, 0.f };
    float o[8][4] = {};

    const int kb_max = 2 * qb + 1;
    for (int kb = 0; kb <= kb_max; kb++) {
        __syncthreads();
        // Load K (f [0,64)) and V (f [128,192)), round to tf32
#pragma unroll
        for (int i = 0; i < 4; i++) {
            int u = t + 256 * i;
            int r = u >> 4, c4 = (u & 15) << 2;
            const float* rp = base + (size_t)(kb * 64 + r) * FDIM;
            float4 kv = *(const float4*)(rp + c4);
            float4 vv = *(const float4*)(rp + 128 + c4);
            uint4 ku, vu;
            ku.x = f2tf(kv.x); ku.y = f2tf(kv.y); ku.z = f2tf(kv.z); ku.w = f2tf(kv.w);
            vu.x = f2tf(vv.x); vu.y = f2tf(vv.y); vu.z = f2tf(vv.z); vu.w = f2tf(vv.w);
            *(uint4*)&Ks[r * 68 + c4] = ku;
            *(uint4*)&Vs[r * 68 + c4] = vu;
        }
        __syncthreads();

        // S = Q @ K^T : warp rows [w*16, w*16+16), cols 64
        float s[8][4] = {};
#pragma unroll
        for (int ks = 0; ks < 8; ks++) {
            const int k8 = ks << 3;
            unsigned af[4];
            const int qr = w * 16 + g;
            af[0] = Qs[qr * 68 + k8 + tc];
            af[1] = Qs[(qr + 8) * 68 + k8 + tc];
            af[2] = Qs[qr * 68 + k8 + tc + 4];
            af[3] = Qs[(qr + 8) * 68 + k8 + tc + 4];
#pragma unroll
            for (int j = 0; j < 8; j++) {
                unsigned bf[2];
                const int kr = j * 8 + g;
                bf[0] = Ks[kr * 68 + k8 + tc];
                bf[1] = Ks[kr * 68 + k8 + tc + 4];
                mma_tf32(s[j], af, bf);
            }
        }

        // Causal mask (only the two diagonal-adjacent key blocks need it)
        if (kb >= 2 * qb) {
            const int row0 = qb * 128 + w * 16 + g;
            const int row1 = row0 + 8;
#pragma unroll
            for (int j = 0; j < 8; j++) {
                const int col = kb * 64 + j * 8 + 2 * tc;
                if (col > row0)     s[j][0] = -1e30f;
                if (col + 1 > row0) s[j][1] = -1e30f;
                if (col > row1)     s[j][2] = -1e30f;
                if (col + 1 > row1) s[j][3] = -1e30f;
            }
        }

        // Online softmax: two rows per thread (g, g+8); row spread over quad (tc)
        float mx0 = -1e30f, mx1 = -1e30f;
#pragma unroll
        for (int j = 0; j < 8; j++) {
            mx0 = fmaxf(mx0, fmaxf(s[j][0], s[j][1]));
            mx1 = fmaxf(mx1, fmaxf(s[j][2], s[j][3]));
        }
#pragma unroll
        for (int msk = 1; msk <= 2; msk <<= 1) {
            mx0 = fmaxf(mx0, __shfl_xor_sync(0xffffffffu, mx0, msk));
            mx1 = fmaxf(mx1, __shfl_xor_sync(0xffffffffu, mx1, msk));
        }
        const float mn0 = fmaxf(m_[0], mx0);
        const float mn1 = fmaxf(m_[1], mx1);
        const float corr0 = __expf(m_[0] - mn0);
        const float corr1 = __expf(m_[1] - mn1);
        m_[0] = mn0; m_[1] = mn1;

        float sum0 = 0.f, sum1 = 0.f;
#pragma unroll
        for (int j = 0; j < 8; j++) {
            s[j][0] = __expf(s[j][0] - mn0);
            s[j][1] = __expf(s[j][1] - mn0);
            s[j][2] = __expf(s[j][2] - mn1);
            s[j][3] = __expf(s[j][3] - mn1);
            sum0 += s[j][0] + s[j][1];
            sum1 += s[j][2] + s[j][3];
        }
#pragma unroll
        for (int msk = 1; msk <= 2; msk <<= 1) {
            sum0 += __shfl_xor_sync(0xffffffffu, sum0, msk);
            sum1 += __shfl_xor_sync(0xffffffffu, sum1, msk);
        }
        l_[0] = l_[0] * corr0 + sum0;
        l_[1] = l_[1] * corr1 + sum1;
#pragma unroll
        for (int j = 0; j < 8; j++) {
            o[j][0] *= corr0; o[j][1] *= corr0;
            o[j][2] *= corr1; o[j][3] *= corr1;
        }

        // P -> smem (tf32), own warp rows only
        {
            const int pr = w * 16 + g;
#pragma unroll
            for (int j = 0; j < 8; j++) {
                const int pc = j * 8 + 2 * tc;
                uint2 p0, p1;
                p0.x = f2tf(s[j][0]); p0.y = f2tf(s[j][1]);
                p1.x = f2tf(s[j][2]); p1.y = f2tf(s[j][3]);
                *(uint2*)&Ps[pr * 68 + pc] = p0;
                *(uint2*)&Ps[(pr + 8) * 68 + pc] = p1;
            }
        }
        __syncwarp();

        // O += P @ V
#pragma unroll
        for (int ks = 0; ks < 8; ks++) {
            const int k8 = ks << 3;
            unsigned af[4];
            const int pr = w * 16 + g;
            af[0] = Ps[pr * 68 + k8 + tc];
            af[1] = Ps[(pr + 8) * 68 + k8 + tc];
            af[2] = Ps[pr * 68 + k8 + tc + 4];
            af[3] = Ps[(pr + 8) * 68 + k8 + tc + 4];
#pragma unroll
            for (int j = 0; j < 8; j++) {
                unsigned bf[2];
                bf[0] = Vs[(k8 + tc) * 68 + j * 8 + g];
                bf[1] = Vs[(k8 + tc + 4) * 68 + j * 8 + g];
                mma_tf32(o[j], af, bf);
            }
        }
    }

    // Normalize, write head-concat: g_sa[b][qb*128 + row][h*64 + col]
    const float inv0 = 1.0f / l_[0];
    const float inv1 = 1.0f / l_[1];
    const int row0 = qb * 128 + w * 16 + g;
    float* outp = g_sa + ((size_t)b * NTOK + row0) * EDIM + h * 64;
#pragma unroll
    for (int j = 0; j < 8; j++) {
        const int col = j * 8 + 2 * tc;
        float2 o0, o1;
        o0.x = o[j][0] * inv0; o0.y = o[j][1] * inv0;
        o1.x = o[j][2] * inv1; o1.y = o[j][3] * inv1;
        *(float2*)(outp + col) = o0;
        *(float2*)(outp + (size_t)8 * EDIM + col) = o1;
    }
}

extern "C" void kernel_launch(void* const* d_in, const int* in_sizes, int n_in,
                              void* d_out, int out_size)
{
    const float* x    = (const float*)d_in[0];
    const float* Wqkv = (const float*)d_in[1];
    const float* bqkv = (const float*)d_in[2];
    const float* Wout = (const float*)d_in[3];
    const float* bout = (const float*)d_in[4];
    float* out = (float*)d_out;

    cudaFuncSetAttribute(attn_kernel, cudaFuncAttributeMaxDynamicSharedMemorySize,
                         ATT_SMEM_WORDS * 4);
    cudaFuncSetAttribute(qkv_gemm_kernel, cudaFuncAttributeMaxDynamicSharedMemorySize,
                         GEMM_SMEM_BYTES);
    cudaFuncSetAttribute(out_gemm_kernel, cudaFuncAttributeMaxDynamicSharedMemorySize,
                         GEMM_SMEM_BYTES);

    // 1) QKV projection: grid (192/64, 2048/128, B*H)
    dim3 g1(FDIM / 64, NTOK / 128, BSZ * NHEAD);
    qkv_gemm_kernel<<<g1, 256, GEMM_SMEM_BYTES>>>(x, Wqkv, bqkv);

    // 2) Causal flash attention: grid (N/128, B*H)
    dim3 g2(NTOK / 128, BSZ * NHEAD);
    attn_kernel<<<g2, 256, ATT_SMEM_WORDS * 4>>>();

    // 3) Output projection: grid (E/64, B*N/128)
    dim3 g3(EDIM / 64, (BSZ * NTOK) / 128);
    out_gemm_kernel<<<g3, 256, GEMM_SMEM_BYTES>>>(Wout, bout, out);
}

// round 17
// speedup vs baseline: 1.5130x; 1.5130x over previous
#include <cuda_runtime.h>

// Problem constants
#define BSZ 2
#define NTOK 2048
#define EDIM 1024
#define NHEAD 16
#define HDIM 64
#define FDIM 192   // 3 * HDIM, order: k | q | v

// Scratch (static device memory — no allocation)
__device__ float g_proj[(size_t)BSZ * NHEAD * NTOK * FDIM]; // [z][n][f], z = b*H+h
__device__ float g_sa[(size_t)BSZ * NTOK * EDIM];           // [b][n][e]

// ---------------------------------------------------------------------------
// tf32 helpers
// ---------------------------------------------------------------------------
__device__ __forceinline__ unsigned f2tf(float x) {
    unsigned u;
    asm("cvt.rna.tf32.f32 %0, %1;" : "=r"(u) : "f"(x));
    return u;
}

__device__ __forceinline__ void mma_tf32(float c[4], const unsigned a[4], const unsigned b[2]) {
    asm volatile(
        "mma.sync.aligned.m16n8k8.row.col.f32.tf32.tf32.f32 "
        "{%0,%1,%2,%3},{%4,%5,%6,%7},{%8,%9},{%0,%1,%2,%3};"
        : "+f"(c[0]), "+f"(c[1]), "+f"(c[2]), "+f"(c[3])
        : "r"(a[0]), "r"(a[1]), "r"(a[2]), "r"(a[3]), "r"(b[0]), "r"(b[1]));
}

// ---------------------------------------------------------------------------
// tf32 GEMM: C[128 x 64] tile = A(MxK) @ B(KxN) + bias, 256 threads, 8 warps.
// Warp layout 4(M) x 2(N): warp tile 32x32 = 2 m16 x 4 n8 mma tiles.
// As stride 36 (=4 mod 32): A-fragment LDS conflict-free.
// ROUND-4-PROVEN dataflow; only the MMA section is register-double-buffered:
// fragments for ks+1 are loaded while ks's MMAs issue.
// ---------------------------------------------------------------------------
__device__ __forceinline__ void gemm_tf32_tile(
    const float* __restrict__ A, int lda,
    const float* __restrict__ B, int ldb,
    const float* __restrict__ bias,
    float* __restrict__ C, int ldc,
    int K, int bm, int bn)
{
    __shared__ unsigned As[128][36];
    __shared__ unsigned Bs[32][68];

    const int t = threadIdx.x;
    const int w = t >> 5, lane = t & 31;
    const int g = lane >> 2, tc = lane & 3;
    const int wm = w >> 1, wn = w & 1;

    const int ar = t >> 3;          // 0..31
    const int ac = (t & 7) << 2;    // 0,4..28
    const int br = t >> 3;          // 0..31
    const int bc = (t & 7) << 3;    // 0,8..56

    float4 aReg[4], bReg[2];

    auto loadG = [&](int k0) {
#pragma unroll
        for (int i = 0; i < 4; i++)
            aReg[i] = *(const float4*)(A + (size_t)(bm + ar + 32 * i) * lda + k0 + ac);
        bReg[0] = *(const float4*)(B + (size_t)(k0 + br) * ldb + bn + bc);
        bReg[1] = *(const float4*)(B + (size_t)(k0 + br) * ldb + bn + bc + 4);
    };

    auto loadFrag = [&](int ks, unsigned af[2][4], unsigned bf[4][2]) {
        const int k8 = ks << 3;
#pragma unroll
        for (int mt = 0; mt < 2; mt++) {
            const int m = wm * 32 + mt * 16;
            af[mt][0] = As[m + g][k8 + tc];
            af[mt][1] = As[m + g + 8][k8 + tc];
            af[mt][2] = As[m + g][k8 + tc + 4];
            af[mt][3] = As[m + g + 8][k8 + tc + 4];
        }
#pragma unroll
        for (int j = 0; j < 4; j++) {
            const int n = wn * 32 + j * 8 + g;
            bf[j][0] = Bs[k8 + tc][n];
            bf[j][1] = Bs[k8 + tc + 4][n];
        }
    };

    float acc[2][4][4] = {};
    loadG(0);

    for (int k0 = 0; k0 < K; k0 += 32) {
        __syncthreads();
#pragma unroll
        for (int i = 0; i < 4; i++) {
            uint4 u;
            u.x = f2tf(aReg[i].x); u.y = f2tf(aReg[i].y);
            u.z = f2tf(aReg[i].z); u.w = f2tf(aReg[i].w);
            *(uint4*)&As[ar + 32 * i][ac] = u;
        }
        {
            uint4 u0, u1;
            u0.x = f2tf(bReg[0].x); u0.y = f2tf(bReg[0].y);
            u0.z = f2tf(bReg[0].z); u0.w = f2tf(bReg[0].w);
            u1.x = f2tf(bReg[1].x); u1.y = f2tf(bReg[1].y);
            u1.z = f2tf(bReg[1].z); u1.w = f2tf(bReg[1].w);
            *(uint4*)&Bs[br][bc] = u0;
            *(uint4*)&Bs[br][bc + 4] = u1;
        }
        __syncthreads();
        if (k0 + 32 < K) loadG(k0 + 32);

        // MMA section: register-double-buffered fragments
        unsigned afd[2][2][4], bfd[2][4][2];
        loadFrag(0, afd[0], bfd[0]);
#pragma unroll
        for (int ks = 0; ks < 4; ks++) {
            const int cur = ks & 1;
            if (ks < 3) loadFrag(ks + 1, afd[cur ^ 1], bfd[cur ^ 1]);
#pragma unroll
            for (int j = 0; j < 4; j++)
#pragma unroll
                for (int mt = 0; mt < 2; mt++)
                    mma_tf32(acc[mt][j], afd[cur][mt], bfd[cur][j]);
        }
    }

    // Epilogue: C(row, col) with row = bm + wm*32 + mt*16 + g (+8), col = bn + wn*32 + j*8 + 2tc (+1)
#pragma unroll
    for (int mt = 0; mt < 2; mt++) {
        const int row0 = bm + wm * 32 + mt * 16 + g;
#pragma unroll
        for (int j = 0; j < 4; j++) {
            const int col = bn + wn * 32 + j * 8 + 2 * tc;
            const float2 bv = *(const float2*)(bias + col);
            float2 o0, o1;
            o0.x = acc[mt][j][0] + bv.x; o0.y = acc[mt][j][1] + bv.y;
            o1.x = acc[mt][j][2] + bv.x; o1.y = acc[mt][j][3] + bv.y;
            *(float2*)(C + (size_t)row0 * ldc + col) = o0;
            *(float2*)(C + (size_t)(row0 + 8) * ldc + col) = o1;
        }
    }
}

// QKV projection: per (b,h): proj[z] = x[b] (N x E) @ Wqkv[h] (E x 192) + bqkv[h]
__global__ void qkv_gemm_kernel(const float* __restrict__ x,
                                const float* __restrict__ Wqkv,
                                const float* __restrict__ bqkv)
{
    const int z = blockIdx.z;
    const int b = z >> 4, h = z & 15;
    gemm_tf32_tile(x + (size_t)b * NTOK * EDIM, EDIM,
                   Wqkv + (size_t)h * EDIM * FDIM, FDIM,
                   bqkv + h * FDIM,
                   g_proj + (size_t)z * NTOK * FDIM, FDIM,
                   EDIM, blockIdx.y * 128, blockIdx.x * 64);
}

// Output projection: out = g_sa (B*N x E) @ Wout (E x E) + bout
__global__ void out_gemm_kernel(const float* __restrict__ Wout,
                                const float* __restrict__ bout,
                                float* __restrict__ out)
{
    gemm_tf32_tile(g_sa, EDIM, Wout, EDIM, bout, out, EDIM,
                   EDIM, blockIdx.y * 128, blockIdx.x * 64);
}

// ---------------------------------------------------------------------------
// Flash attention with tf32 mma — VERBATIM round-4 body (proven), with one
// change: heavy (high-qb) blocks launch first for better wave tail packing.
// ---------------------------------------------------------------------------
#define ATT_SMEM_WORDS (128 * 68 + 64 * 68 + 64 * 68 + 128 * 68)

__global__ void attn_kernel()
{
    extern __shared__ unsigned sm[];
    unsigned* Qs = sm;                  // [128][68]
    unsigned* Ks = Qs + 128 * 68;       // [64][68]
    unsigned* Vs = Ks + 64 * 68;        // [64][68]
    unsigned* Ps = Vs + 64 * 68;        // [128][68]

    const int z = blockIdx.y;
    const int b = z >> 4, h = z & 15;
    const int qb = (int)gridDim.x - 1 - (int)blockIdx.x;  // heavy blocks first
    const float* base = g_proj + (size_t)z * NTOK * FDIM;

    const int t = threadIdx.x;
    const int w = t >> 5, lane = t & 31;
    const int g = lane >> 2, tc = lane & 3;

    // Load Q (f in [64,128)), scale by 1/8, round to tf32
#pragma unroll
    for (int i = 0; i < 8; i++) {
        int u = t + 256 * i;
        int r = u >> 4, c4 = (u & 15) << 2;
        float4 v = *(const float4*)(base + (size_t)(qb * 128 + r) * FDIM + 64 + c4);
        uint4 q;
        q.x = f2tf(v.x * 0.125f); q.y = f2tf(v.y * 0.125f);
        q.z = f2tf(v.z * 0.125f); q.w = f2tf(v.w * 0.125f);
        *(uint4*)&Qs[r * 68 + c4] = q;
    }

    float m_[2] = { -1e30f, -1e30f };
    float l_[2] = { 0.f, 0.f };
    float o[8][4] = {};

    const int kb_max = 2 * qb + 1;
    for (int kb = 0; kb <= kb_max; kb++) {
        __syncthreads();
        // Load K (f [0,64)) and V (f [128,192)), round to tf32
#pragma unroll
        for (int i = 0; i < 4; i++) {
            int u = t + 256 * i;
            int r = u >> 4, c4 = (u & 15) << 2;
            const float* rp = base + (size_t)(kb * 64 + r) * FDIM;
            float4 kv = *(const float4*)(rp + c4);
            float4 vv = *(const float4*)(rp + 128 + c4);
            uint4 ku, vu;
            ku.x = f2tf(kv.x); ku.y = f2tf(kv.y); ku.z = f2tf(kv.z); ku.w = f2tf(kv.w);
            vu.x = f2tf(vv.x); vu.y = f2tf(vv.y); vu.z = f2tf(vv.z); vu.w = f2tf(vv.w);
            *(uint4*)&Ks[r * 68 + c4] = ku;
            *(uint4*)&Vs[r * 68 + c4] = vu;
        }
        __syncthreads();

        // S = Q @ K^T : warp rows [w*16, w*16+16), cols 64
        float s[8][4] = {};
#pragma unroll
        for (int ks = 0; ks < 8; ks++) {
            const int k8 = ks << 3;
            unsigned af[4];
            const int qr = w * 16 + g;
            af[0] = Qs[qr * 68 + k8 + tc];
            af[1] = Qs[(qr + 8) * 68 + k8 + tc];
            af[2] = Qs[qr * 68 + k8 + tc + 4];
            af[3] = Qs[(qr + 8) * 68 + k8 + tc + 4];
#pragma unroll
            for (int j = 0; j < 8; j++) {
                unsigned bf[2];
                const int kr = j * 8 + g;
                bf[0] = Ks[kr * 68 + k8 + tc];
                bf[1] = Ks[kr * 68 + k8 + tc + 4];
                mma_tf32(s[j], af, bf);
            }
        }

        // Causal mask (only the two diagonal-adjacent key blocks need it)
        if (kb >= 2 * qb) {
            const int row0 = qb * 128 + w * 16 + g;
            const int row1 = row0 + 8;
#pragma unroll
            for (int j = 0; j < 8; j++) {
                const int col = kb * 64 + j * 8 + 2 * tc;
                if (col > row0)     s[j][0] = -1e30f;
                if (col + 1 > row0) s[j][1] = -1e30f;
                if (col > row1)     s[j][2] = -1e30f;
                if (col + 1 > row1) s[j][3] = -1e30f;
            }
        }

        // Online softmax: two rows per thread (g, g+8); row spread over quad (tc)
        float mx0 = -1e30f, mx1 = -1e30f;
#pragma unroll
        for (int j = 0; j < 8; j++) {
            mx0 = fmaxf(mx0, fmaxf(s[j][0], s[j][1]));
            mx1 = fmaxf(mx1, fmaxf(s[j][2], s[j][3]));
        }
#pragma unroll
        for (int msk = 1; msk <= 2; msk <<= 1) {
            mx0 = fmaxf(mx0, __shfl_xor_sync(0xffffffffu, mx0, msk));
            mx1 = fmaxf(mx1, __shfl_xor_sync(0xffffffffu, mx1, msk));
        }
        const float mn0 = fmaxf(m_[0], mx0);
        const float mn1 = fmaxf(m_[1], mx1);
        const float corr0 = __expf(m_[0] - mn0);
        const float corr1 = __expf(m_[1] - mn1);
        m_[0] = mn0; m_[1] = mn1;

        float sum0 = 0.f, sum1 = 0.f;
#pragma unroll
        for (int j = 0; j < 8; j++) {
            s[j][0] = __expf(s[j][0] - mn0);
            s[j][1] = __expf(s[j][1] - mn0);
            s[j][2] = __expf(s[j][2] - mn1);
            s[j][3] = __expf(s[j][3] - mn1);
            sum0 += s[j][0] + s[j][1];
            sum1 += s[j][2] + s[j][3];
        }
#pragma unroll
        for (int msk = 1; msk <= 2; msk <<= 1) {
            sum0 += __shfl_xor_sync(0xffffffffu, sum0, msk);
            sum1 += __shfl_xor_sync(0xffffffffu, sum1, msk);
        }
        l_[0] = l_[0] * corr0 + sum0;
        l_[1] = l_[1] * corr1 + sum1;
#pragma unroll
        for (int j = 0; j < 8; j++) {
            o[j][0] *= corr0; o[j][1] *= corr0;
            o[j][2] *= corr1; o[j][3] *= corr1;
        }

        // P -> smem (tf32), own warp rows only
        {
            const int pr = w * 16 + g;
#pragma unroll
            for (int j = 0; j < 8; j++) {
                const int pc = j * 8 + 2 * tc;
                uint2 p0, p1;
                p0.x = f2tf(s[j][0]); p0.y = f2tf(s[j][1]);
                p1.x = f2tf(s[j][2]); p1.y = f2tf(s[j][3]);
                *(uint2*)&Ps[pr * 68 + pc] = p0;
                *(uint2*)&Ps[(pr + 8) * 68 + pc] = p1;
            }
        }
        __syncwarp();

        // O += P @ V
#pragma unroll
        for (int ks = 0; ks < 8; ks++) {
            const int k8 = ks << 3;
            unsigned af[4];
            const int pr = w * 16 + g;
            af[0] = Ps[pr * 68 + k8 + tc];
            af[1] = Ps[(pr + 8) * 68 + k8 + tc];
            af[2] = Ps[pr * 68 + k8 + tc + 4];
            af[3] = Ps[(pr + 8) * 68 + k8 + tc + 4];
#pragma unroll
            for (int j = 0; j < 8; j++) {
                unsigned bf[2];
                bf[0] = Vs[(k8 + tc) * 68 + j * 8 + g];
                bf[1] = Vs[(k8 + tc + 4) * 68 + j * 8 + g];
                mma_tf32(o[j], af, bf);
            }
        }
    }

    // Normalize, write head-concat: g_sa[b][qb*128 + row][h*64 + col]
    const float inv0 = 1.0f / l_[0];
    const float inv1 = 1.0f / l_[1];
    const int row0 = qb * 128 + w * 16 + g;
    float* outp = g_sa + ((size_t)b * NTOK + row0) * EDIM + h * 64;
#pragma unroll
    for (int j = 0; j < 8; j++) {
        const int col = j * 8 + 2 * tc;
        float2 o0, o1;
        o0.x = o[j][0] * inv0; o0.y = o[j][1] * inv0;
        o1.x = o[j][2] * inv1; o1.y = o[j][3] * inv1;
        *(float2*)(outp + col) = o0;
        *(float2*)(outp + (size_t)8 * EDIM + col) = o1;
    }
}

extern "C" void kernel_launch(void* const* d_in, const int* in_sizes, int n_in,
                              void* d_out, int out_size)
{
    const float* x    = (const float*)d_in[0];
    const float* Wqkv = (const float*)d_in[1];
    const float* bqkv = (const float*)d_in[2];
    const float* Wout = (const float*)d_in[3];
    const float* bout = (const float*)d_in[4];
    float* out = (float*)d_out;

    cudaFuncSetAttribute(attn_kernel, cudaFuncAttributeMaxDynamicSharedMemorySize,
                         ATT_SMEM_WORDS * 4);

    // 1) QKV projection: grid (192/64, 2048/128, B*H)
    dim3 g1(FDIM / 64, NTOK / 128, BSZ * NHEAD);
    qkv_gemm_kernel<<<g1, 256>>>(x, Wqkv, bqkv);

    // 2) Causal flash attention: grid (N/128, B*H)
    dim3 g2(NTOK / 128, BSZ * NHEAD);
    attn_kernel<<<g2, 256, ATT_SMEM_WORDS * 4>>>();

    // 3) Output projection: grid (E/64, B*N/128)
    dim3 g3(EDIM / 64, (BSZ * NTOK) / 128);
    out_gemm_kernel<<<g3, 256>>>(Wout, bout, out);
}